// round 13
// baseline (speedup 1.0000x reference)
#include <cuda_runtime.h>
#include <cuda_fp16.h>
#include <cuda_bf16.h>
#include <cstdint>

#define N_NODES_MAX 100000
#define E_MAX       1600000
#define K_DIM       256
#define H_DIM       128
#define SCAN_B      1024
#define NB_MAX      ((N_NODES_MAX + SCAN_B - 1) / SCAN_B)   // 98

// ---------------- device scratch (static, no allocation) ----------------
__device__ __half g_h[(size_t)N_NODES_MAX * H_DIM];  // h = x@W (UNSCALED, fp16)
__device__ int    g_count[N_NODES_MAX];
__device__ int    g_off[N_NODES_MAX + 1];
__device__ int    g_cursor[N_NODES_MAX];
__device__ float  g_dinv[N_NODES_MAX];
__device__ int    g_src[E_MAX];
__device__ int    g_bsum[NB_MAX + 1];
__device__ int    g_is64;
__device__ int    g_swap;

// ---------------- probe: dtype of edge buffer + b/alpha order ----------------
__global__ void detect_kernel(const int* __restrict__ e,
                              const float* __restrict__ pb,
                              const float* __restrict__ pa) {
    int lane = threadIdx.x & 31;
    int nz = (e[2 * lane + 1] != 0) ? 1 : 0;     // odd words zero <=> int64
    unsigned m = __ballot_sync(0xFFFFFFFFu, nz);
    if (lane == 0) {
        g_is64 = (m == 0u) ? 1 : 0;
        g_swap = (pb[0] != 0.0f && pa[0] == 0.0f) ? 1 : 0;
    }
}

__device__ __forceinline__ int edge_val(const int* e, long long idx) {
    return g_is64 ? e[2 * idx] : e[(size_t)idx];
}

// ---------------- build CSR-by-destination ----------------
__global__ void zero_count_kernel(int n) {
    int i = blockIdx.x * blockDim.x + threadIdx.x;
    if (i < n) g_count[i] = 0;
}

__global__ void hist_kernel(const int* __restrict__ e, int E, int N) {
    int i = blockIdx.x * blockDim.x + threadIdx.x;
    if (i >= E) return;
    unsigned c = (unsigned)edge_val(e, (long long)E + i);
    if (c < (unsigned)N) atomicAdd(&g_count[c], 1);
}

__global__ __launch_bounds__(SCAN_B) void scanA_kernel(int N) {
    __shared__ int sm[SCAN_B];
    const int tid = threadIdx.x;
    const int i = blockIdx.x * SCAN_B + tid;
    int v = (i < N) ? g_count[i] : 0;
    sm[tid] = v;
    __syncthreads();
#pragma unroll
    for (int d = 1; d < SCAN_B; d <<= 1) {
        int t = sm[tid];
        int add = (tid >= d) ? sm[tid - d] : 0;
        __syncthreads();
        sm[tid] = t + add;
        __syncthreads();
    }
    if (i < N) g_off[i] = sm[tid] - v;
    if (tid == SCAN_B - 1) g_bsum[blockIdx.x] = sm[tid];
}

__global__ void scanB_kernel(int nb) {
    __shared__ int sm[128];
    const int tid = threadIdx.x;
    int v = (tid < nb) ? g_bsum[tid] : 0;
    sm[tid] = v;
    __syncthreads();
#pragma unroll
    for (int d = 1; d < 128; d <<= 1) {
        int t = sm[tid];
        int add = (tid >= d) ? sm[tid - d] : 0;
        __syncthreads();
        sm[tid] = t + add;
        __syncthreads();
    }
    if (tid < nb) g_bsum[tid] = sm[tid] - v;
}

__global__ void scanC_kernel(int N) {
    int i = blockIdx.x * blockDim.x + threadIdx.x;
    if (i >= N) return;
    int cnt = g_count[i];
    int off = g_off[i] + g_bsum[i >> 10];
    g_off[i] = off;
    g_cursor[i] = off;
    g_dinv[i] = rsqrtf((float)cnt + 1.0f);
    if (i == N - 1) g_off[N] = off + cnt;
}

__global__ void scatter_src_kernel(const int* __restrict__ e, int E, int N) {
    int i = blockIdx.x * blockDim.x + threadIdx.x;
    if (i >= E) return;
    unsigned r = (unsigned)edge_val(e, i);
    unsigned c = (unsigned)edge_val(e, (long long)E + i);
    if (r < (unsigned)N && c < (unsigned)N) {
        int p = atomicAdd(&g_cursor[c], 1);
        if ((unsigned)p < (unsigned)E) g_src[p] = (int)r;
    }
}

// ---------------- tf32 tensor-core GEMM: g_h = x @ W (fp16 out) ----------------
// CTA 128x128, 8 warps (4M x 2N), warp tile 32x64, k-slice 16, double buffer.
#define BM 128
#define BN 128
#define BKT 16
#define SMP (BM + 8)   // padded stride: bank = 8*tig + gid -> conflict-free

__device__ __forceinline__ uint32_t f2tf(float f) {
    uint32_t u;
    asm("cvt.rna.tf32.f32 %0, %1;" : "=r"(u) : "f"(f));
    return u;
}

__global__ __launch_bounds__(256) void gemm_tf32_kernel(const float* __restrict__ A,
                                                        const float* __restrict__ Bw,
                                                        int M) {
    __shared__ uint32_t As[2][BKT][SMP];   // [buf][k][m]
    __shared__ uint32_t Bs[2][BKT][SMP];   // [buf][k][n]
    const int tid = threadIdx.x;
    const int brow = blockIdx.x * BM;
    const int wid = tid >> 5;
    const int lane = tid & 31;
    const int gid = lane >> 2;       // 0..7
    const int tig = lane & 3;        // 0..3
    const int mrow0 = (wid & 3) * 32;
    const int ncol0 = (wid >> 2) * 64;

    float acc[2][8][4];
#pragma unroll
    for (int mt = 0; mt < 2; mt++)
#pragma unroll
        for (int nt = 0; nt < 8; nt++)
#pragma unroll
            for (int q = 0; q < 4; q++) acc[mt][nt][q] = 0.0f;

    // ---- stage slice 0 into buffer 0 ----
#pragma unroll
    for (int t = 0; t < 2; t++) {
        int v = tid + t * 256;
        int r = v >> 2;              // 0..127 (m)
        int kc = (v & 3) * 4;        // 0,4,8,12 (k)
        int grow = brow + r;
        float4 a = (grow < M) ? *(const float4*)(A + (size_t)grow * K_DIM + kc)
                              : make_float4(0.f, 0.f, 0.f, 0.f);
        As[0][kc + 0][r] = f2tf(a.x);
        As[0][kc + 1][r] = f2tf(a.y);
        As[0][kc + 2][r] = f2tf(a.z);
        As[0][kc + 3][r] = f2tf(a.w);
    }
#pragma unroll
    for (int t = 0; t < 2; t++) {
        int v = tid + t * 256;
        int r = v >> 5;              // 0..15 (k)
        int c = (v & 31) * 4;        // 0..124 (n)
        float4 b = *(const float4*)(Bw + (size_t)r * BN + c);
        Bs[0][r][c + 0] = f2tf(b.x);
        Bs[0][r][c + 1] = f2tf(b.y);
        Bs[0][r][c + 2] = f2tf(b.z);
        Bs[0][r][c + 3] = f2tf(b.w);
    }
    __syncthreads();

    const int NS = K_DIM / BKT;      // 16
    for (int kt = 0; kt < NS; kt++) {
        const int cur = kt & 1;
        const int nxt = cur ^ 1;

        // prefetch next slice into registers
        float4 pa[2], pb[2];
        if (kt + 1 < NS) {
            int kbase = (kt + 1) * BKT;
#pragma unroll
            for (int t = 0; t < 2; t++) {
                int v = tid + t * 256;
                int r = v >> 2;
                int kc = (v & 3) * 4;
                int grow = brow + r;
                pa[t] = (grow < M)
                    ? *(const float4*)(A + (size_t)grow * K_DIM + kbase + kc)
                    : make_float4(0.f, 0.f, 0.f, 0.f);
                int rb = v >> 5;
                int cb = (v & 31) * 4;
                pb[t] = *(const float4*)(Bw + (size_t)(kbase + rb) * BN + cb);
            }
        }

        // compute: two k8 halves of this 16-wide slice
#pragma unroll
        for (int kh = 0; kh < 2; kh++) {
            const int k0 = kh * 8;
            uint32_t bfr[8][2];
#pragma unroll
            for (int nt = 0; nt < 8; nt++) {
                bfr[nt][0] = Bs[cur][k0 + tig][ncol0 + nt * 8 + gid];
                bfr[nt][1] = Bs[cur][k0 + tig + 4][ncol0 + nt * 8 + gid];
            }
#pragma unroll
            for (int mt = 0; mt < 2; mt++) {
                const int mb = mrow0 + mt * 16;
                uint32_t a0 = As[cur][k0 + tig][mb + gid];
                uint32_t a1 = As[cur][k0 + tig][mb + gid + 8];
                uint32_t a2 = As[cur][k0 + tig + 4][mb + gid];
                uint32_t a3 = As[cur][k0 + tig + 4][mb + gid + 8];
#pragma unroll
                for (int nt = 0; nt < 8; nt++) {
                    asm volatile(
                        "mma.sync.aligned.m16n8k8.row.col.f32.tf32.tf32.f32 "
                        "{%0,%1,%2,%3}, {%4,%5,%6,%7}, {%8,%9}, {%0,%1,%2,%3};"
                        : "+f"(acc[mt][nt][0]), "+f"(acc[mt][nt][1]),
                          "+f"(acc[mt][nt][2]), "+f"(acc[mt][nt][3])
                        : "r"(a0), "r"(a1), "r"(a2), "r"(a3),
                          "r"(bfr[nt][0]), "r"(bfr[nt][1]));
                }
            }
        }

        if (kt + 1 < NS) {
            __syncthreads();   // all warps done computing before overwrite
#pragma unroll
            for (int t = 0; t < 2; t++) {
                int v = tid + t * 256;
                int r = v >> 2;
                int kc = (v & 3) * 4;
                As[nxt][kc + 0][r] = f2tf(pa[t].x);
                As[nxt][kc + 1][r] = f2tf(pa[t].y);
                As[nxt][kc + 2][r] = f2tf(pa[t].z);
                As[nxt][kc + 3][r] = f2tf(pa[t].w);
                int rb = v >> 5;
                int cb = (v & 31) * 4;
                Bs[nxt][rb][cb + 0] = f2tf(pb[t].x);
                Bs[nxt][rb][cb + 1] = f2tf(pb[t].y);
                Bs[nxt][rb][cb + 2] = f2tf(pb[t].z);
                Bs[nxt][rb][cb + 3] = f2tf(pb[t].w);
            }
            __syncthreads();   // stores visible before next iteration reads
        }
    }

    // ---- epilogue: convert to fp16, store ----
#pragma unroll
    for (int mt = 0; mt < 2; mt++) {
#pragma unroll
        for (int nt = 0; nt < 8; nt++) {
            int r0 = brow + mrow0 + mt * 16 + gid;
            int col = ncol0 + nt * 8 + 2 * tig;
            if (r0 < M) {
                __half2 p0 = __floats2half2_rn(acc[mt][nt][0], acc[mt][nt][1]);
                *(__half2*)(g_h + (size_t)r0 * H_DIM + col) = p0;
            }
            if (r0 + 8 < M) {
                __half2 p1 = __floats2half2_rn(acc[mt][nt][2], acc[mt][nt][3]);
                *(__half2*)(g_h + (size_t)(r0 + 8) * H_DIM + col) = p1;
            }
        }
    }
}

// ---------------- gather: 2 destinations per warp, LDG.128 per lane ----------
// Half-warp (16 lanes) owns one destination; lane hl covers 8 halves = 16B.
__device__ __forceinline__ void acc_half8(float acc[8], uint4 raw, float d) {
    __half2 h01 = *(__half2*)&raw.x;
    __half2 h23 = *(__half2*)&raw.y;
    __half2 h45 = *(__half2*)&raw.z;
    __half2 h67 = *(__half2*)&raw.w;
    float2 f01 = __half22float2(h01);
    float2 f23 = __half22float2(h23);
    float2 f45 = __half22float2(h45);
    float2 f67 = __half22float2(h67);
    acc[0] = fmaf(f01.x, d, acc[0]);
    acc[1] = fmaf(f01.y, d, acc[1]);
    acc[2] = fmaf(f23.x, d, acc[2]);
    acc[3] = fmaf(f23.y, d, acc[3]);
    acc[4] = fmaf(f45.x, d, acc[4]);
    acc[5] = fmaf(f45.y, d, acc[5]);
    acc[6] = fmaf(f67.x, d, acc[6]);
    acc[7] = fmaf(f67.y, d, acc[7]);
}

__global__ __launch_bounds__(256) void gather_kernel(const float* __restrict__ pb,
                                                     const float* __restrict__ pa,
                                                     float* __restrict__ out, int N) {
    const int gthread = blockIdx.x * blockDim.x + threadIdx.x;
    const int warp = gthread >> 5;
    const int lane = threadIdx.x & 31;
    const int half = lane >> 4;          // 0 or 1
    const int hl = lane & 15;            // 0..15
    const int c = warp * 2 + half;       // destination node for this half-warp
    if (c >= N) return;

    const float dc = g_dinv[c];
    const int s = g_off[c];
    const int e = g_off[c + 1];

    float acc[8];
    {   // self-loop: h[c] * dinv[c]  (whole sum gets * dc at the end)
        uint4 raw = *(const uint4*)(g_h + (size_t)c * H_DIM + hl * 8);
        __half2 h01 = *(__half2*)&raw.x;
        __half2 h23 = *(__half2*)&raw.y;
        __half2 h45 = *(__half2*)&raw.z;
        __half2 h67 = *(__half2*)&raw.w;
        float2 f01 = __half22float2(h01);
        float2 f23 = __half22float2(h23);
        float2 f45 = __half22float2(h45);
        float2 f67 = __half22float2(h67);
        acc[0] = f01.x * dc; acc[1] = f01.y * dc;
        acc[2] = f23.x * dc; acc[3] = f23.y * dc;
        acc[4] = f45.x * dc; acc[5] = f45.y * dc;
        acc[6] = f67.x * dc; acc[7] = f67.y * dc;
    }

    int i = s;
    for (; i + 3 < e; i += 4) {
        int s0 = g_src[i];
        int s1 = g_src[i + 1];
        int s2 = g_src[i + 2];
        int s3 = g_src[i + 3];
        float d0 = g_dinv[s0];
        float d1 = g_dinv[s1];
        float d2 = g_dinv[s2];
        float d3 = g_dinv[s3];
        uint4 v0 = *(const uint4*)(g_h + (size_t)s0 * H_DIM + hl * 8);
        uint4 v1 = *(const uint4*)(g_h + (size_t)s1 * H_DIM + hl * 8);
        uint4 v2 = *(const uint4*)(g_h + (size_t)s2 * H_DIM + hl * 8);
        uint4 v3 = *(const uint4*)(g_h + (size_t)s3 * H_DIM + hl * 8);
        acc_half8(acc, v0, d0);
        acc_half8(acc, v1, d1);
        acc_half8(acc, v2, d2);
        acc_half8(acc, v3, d3);
    }
    for (; i < e; i++) {
        int s0 = g_src[i];
        float d0 = g_dinv[s0];
        uint4 v0 = *(const uint4*)(g_h + (size_t)s0 * H_DIM + hl * 8);
        acc_half8(acc, v0, d0);
    }

    // epilogue: bias + PReLU over this lane's 8 channels [hl*8, hl*8+8)
    float4 bb0 = *(const float4*)(pb + hl * 8);
    float4 bb1 = *(const float4*)(pb + hl * 8 + 4);
    float4 aa0 = *(const float4*)(pa + hl * 8);
    float4 aa1 = *(const float4*)(pa + hl * 8 + 4);
    if (g_swap) {
        float4 t0 = bb0; bb0 = aa0; aa0 = t0;
        float4 t1 = bb1; bb1 = aa1; aa1 = t1;
    }
    float4 r0, r1;
    float t;
    t = fmaf(acc[0], dc, bb0.x); r0.x = (t >= 0.f) ? t : aa0.x * t;
    t = fmaf(acc[1], dc, bb0.y); r0.y = (t >= 0.f) ? t : aa0.y * t;
    t = fmaf(acc[2], dc, bb0.z); r0.z = (t >= 0.f) ? t : aa0.z * t;
    t = fmaf(acc[3], dc, bb0.w); r0.w = (t >= 0.f) ? t : aa0.w * t;
    t = fmaf(acc[4], dc, bb1.x); r1.x = (t >= 0.f) ? t : aa1.x * t;
    t = fmaf(acc[5], dc, bb1.y); r1.y = (t >= 0.f) ? t : aa1.y * t;
    t = fmaf(acc[6], dc, bb1.z); r1.z = (t >= 0.f) ? t : aa1.z * t;
    t = fmaf(acc[7], dc, bb1.w); r1.w = (t >= 0.f) ? t : aa1.w * t;
    *(float4*)(out + (size_t)c * H_DIM + hl * 8) = r0;
    *(float4*)(out + (size_t)c * H_DIM + hl * 8 + 4) = r1;
}

// ---------------- launch (fork-join: GEMM overlaps edge ingestion) ----------------
extern "C" void kernel_launch(void* const* d_in, const int* in_sizes, int n_in,
                              void* d_out, int out_size) {
    int ix = -1, ie = -1, iw = -1;
    for (int pass = 0; pass < 3; pass++) {
        int best = -1;
        long long bs = -1;
        for (int i = 0; i < n_in; i++) {
            if (i == ix || i == ie || i == iw) continue;
            if ((long long)in_sizes[i] > bs) { bs = in_sizes[i]; best = i; }
        }
        if (pass == 0) ix = best; else if (pass == 1) ie = best; else iw = best;
    }
    int ib = -1, ia = -1;
    for (int i = 0; i < n_in; i++) {
        if (i == ix || i == ie || i == iw) continue;
        if (ib < 0) ib = i; else ia = i;
    }

    const float* x = (const float*)d_in[ix];
    const int*   e = (const int*)d_in[ie];
    const float* W = (const float*)d_in[iw];
    const float* b = (const float*)d_in[ib];
    const float* alpha = (const float*)d_in[ia];
    float* out = (float*)d_out;

    const int N = in_sizes[ix] / K_DIM;   // 100000
    const int E = in_sizes[ie] / 2;       // 1600000
    const int NB = (N + SCAN_B - 1) / SCAN_B;
    const int TB = 256;

    static cudaStream_t s2 = nullptr;
    static cudaEvent_t evFork = nullptr, evJoin = nullptr;
    if (s2 == nullptr) {
        cudaStreamCreateWithFlags(&s2, cudaStreamNonBlocking);
        cudaEventCreateWithFlags(&evFork, cudaEventDisableTiming);
        cudaEventCreateWithFlags(&evJoin, cudaEventDisableTiming);
    }

    // fork: GEMM on s2 (depends on nothing device-side)
    cudaEventRecord(evFork, 0);
    cudaStreamWaitEvent(s2, evFork, 0);
    gemm_tf32_kernel<<<(N + BM - 1) / BM, 256, 0, s2>>>(x, W, N);
    cudaEventRecord(evJoin, s2);

    // edge ingestion chain on main stream
    detect_kernel<<<1, 32>>>(e, b, alpha);
    zero_count_kernel<<<(N + TB - 1) / TB, TB>>>(N);
    hist_kernel<<<(E + TB - 1) / TB, TB>>>(e, E, N);
    scanA_kernel<<<NB, SCAN_B>>>(N);
    scanB_kernel<<<1, 128>>>(NB);
    scanC_kernel<<<(N + TB - 1) / TB, TB>>>(N);
    scatter_src_kernel<<<(E + TB - 1) / TB, TB>>>(e, E, N);

    // join, then gather (2 dests per warp => N*16 threads)
    cudaStreamWaitEvent(0, evJoin, 0);
    gather_kernel<<<(int)(((long long)N * 16 + TB - 1) / TB), TB>>>(b, alpha, out, N);
}

// round 15
// speedup vs baseline: 1.0299x; 1.0299x over previous
#include <cuda_runtime.h>
#include <cuda_fp16.h>
#include <cuda_bf16.h>
#include <cstdint>

#define N_NODES_MAX 100000
#define E_MAX       1600000
#define K_DIM       256
#define H_DIM       128
#define SCAN_B      1024
#define NB_MAX      ((N_NODES_MAX + SCAN_B - 1) / SCAN_B)   // 98

// ---------------- device scratch (static, no allocation) ----------------
__device__ __half g_h[(size_t)N_NODES_MAX * H_DIM];  // h = x@W (UNSCALED, fp16)
__device__ int    g_count[N_NODES_MAX];
__device__ int    g_off[N_NODES_MAX + 1];
__device__ float  g_dinv[N_NODES_MAX];
__device__ int    g_src[E_MAX];
__device__ int    g_rank[E_MAX];                     // rank of edge within its dest
__device__ int    g_bsum[NB_MAX + 1];
__device__ int    g_is64;
__device__ int    g_swap;

__device__ __forceinline__ int edge_val(const int* e, long long idx) {
    return g_is64 ? e[2 * idx] : e[(size_t)idx];
}

// ---------------- init: zero counts + dtype/order probe (fused) --------------
__global__ void init_kernel(const int* __restrict__ e,
                            const float* __restrict__ pb,
                            const float* __restrict__ pa, int n) {
    int i = blockIdx.x * blockDim.x + threadIdx.x;
    if (i < n) g_count[i] = 0;
    if (blockIdx.x == 0 && threadIdx.x < 32) {
        int lane = threadIdx.x;
        int nz = (e[2 * lane + 1] != 0) ? 1 : 0;     // odd words zero <=> int64
        unsigned m = __ballot_sync(0xFFFFFFFFu, nz);
        if (lane == 0) {
            g_is64 = (m == 0u) ? 1 : 0;
            g_swap = (pb[0] != 0.0f && pa[0] == 0.0f) ? 1 : 0;
        }
    }
}

// ---------------- hist + per-edge rank (atomic return value) -----------------
__global__ void hist_kernel(const int* __restrict__ e, int E, int N) {
    int i = blockIdx.x * blockDim.x + threadIdx.x;
    if (i >= E) return;
    unsigned c = (unsigned)edge_val(e, (long long)E + i);
    int rk = 0;
    if (c < (unsigned)N) rk = atomicAdd(&g_count[c], 1);
    g_rank[i] = rk;
}

__global__ __launch_bounds__(SCAN_B) void scanA_kernel(int N) {
    __shared__ int sm[SCAN_B];
    const int tid = threadIdx.x;
    const int i = blockIdx.x * SCAN_B + tid;
    int v = (i < N) ? g_count[i] : 0;
    sm[tid] = v;
    __syncthreads();
#pragma unroll
    for (int d = 1; d < SCAN_B; d <<= 1) {
        int t = sm[tid];
        int add = (tid >= d) ? sm[tid - d] : 0;
        __syncthreads();
        sm[tid] = t + add;
        __syncthreads();
    }
    if (i < N) g_off[i] = sm[tid] - v;          // local exclusive
    if (tid == SCAN_B - 1) g_bsum[blockIdx.x] = sm[tid];
}

// scanC: inline bsum-prefix (replaces scanB) + finalize off + dinv.
// 256-thread blocks never straddle a 1024-node bucket (1024 % 256 == 0).
__global__ void scanC_kernel(int N) {
    __shared__ int base_sh;
    const int bucket = blockIdx.x >> 2;          // (blockIdx*256)/1024
    if (threadIdx.x < 32) {
        int s = 0;
        for (int j = threadIdx.x; j < bucket; j += 32) s += g_bsum[j];
#pragma unroll
        for (int o = 16; o; o >>= 1) s += __shfl_down_sync(0xFFFFFFFFu, s, o);
        if (threadIdx.x == 0) base_sh = s;
    }
    __syncthreads();
    int i = blockIdx.x * blockDim.x + threadIdx.x;
    if (i >= N) return;
    int cnt = g_count[i];
    int off = g_off[i] + base_sh;
    g_off[i] = off;
    g_dinv[i] = rsqrtf((float)cnt + 1.0f);       // +1 self loop
    if (i == N - 1) g_off[N] = off + cnt;
}

// ---------------- scatter: NO atomics (uses precomputed rank) ----------------
__global__ void scatter_src_kernel(const int* __restrict__ e, int E, int N) {
    int i = blockIdx.x * blockDim.x + threadIdx.x;
    if (i >= E) return;
    unsigned r = (unsigned)edge_val(e, i);
    unsigned c = (unsigned)edge_val(e, (long long)E + i);
    if (r < (unsigned)N && c < (unsigned)N) {
        int p = g_off[c] + g_rank[i];
        if ((unsigned)p < (unsigned)E_MAX) g_src[p] = (int)r;
    }
}

// ---------------- tf32 tensor-core GEMM: g_h = x @ W (fp16 out) ----------------
#define BM 128
#define BN 128
#define BKT 16
#define SMP (BM + 8)

__device__ __forceinline__ uint32_t f2tf(float f) {
    uint32_t u;
    asm("cvt.rna.tf32.f32 %0, %1;" : "=r"(u) : "f"(f));
    return u;
}

__global__ __launch_bounds__(256) void gemm_tf32_kernel(const float* __restrict__ A,
                                                        const float* __restrict__ Bw,
                                                        int M) {
    __shared__ uint32_t As[2][BKT][SMP];
    __shared__ uint32_t Bs[2][BKT][SMP];
    const int tid = threadIdx.x;
    const int brow = blockIdx.x * BM;
    const int wid = tid >> 5;
    const int lane = tid & 31;
    const int gid = lane >> 2;
    const int tig = lane & 3;
    const int mrow0 = (wid & 3) * 32;
    const int ncol0 = (wid >> 2) * 64;

    float acc[2][8][4];
#pragma unroll
    for (int mt = 0; mt < 2; mt++)
#pragma unroll
        for (int nt = 0; nt < 8; nt++)
#pragma unroll
            for (int q = 0; q < 4; q++) acc[mt][nt][q] = 0.0f;

#pragma unroll
    for (int t = 0; t < 2; t++) {
        int v = tid + t * 256;
        int r = v >> 2;
        int kc = (v & 3) * 4;
        int grow = brow + r;
        float4 a = (grow < M) ? *(const float4*)(A + (size_t)grow * K_DIM + kc)
                              : make_float4(0.f, 0.f, 0.f, 0.f);
        As[0][kc + 0][r] = f2tf(a.x);
        As[0][kc + 1][r] = f2tf(a.y);
        As[0][kc + 2][r] = f2tf(a.z);
        As[0][kc + 3][r] = f2tf(a.w);
    }
#pragma unroll
    for (int t = 0; t < 2; t++) {
        int v = tid + t * 256;
        int r = v >> 5;
        int c = (v & 31) * 4;
        float4 b = *(const float4*)(Bw + (size_t)r * BN + c);
        Bs[0][r][c + 0] = f2tf(b.x);
        Bs[0][r][c + 1] = f2tf(b.y);
        Bs[0][r][c + 2] = f2tf(b.z);
        Bs[0][r][c + 3] = f2tf(b.w);
    }
    __syncthreads();

    const int NS = K_DIM / BKT;
    for (int kt = 0; kt < NS; kt++) {
        const int cur = kt & 1;
        const int nxt = cur ^ 1;

        float4 pa[2], pb[2];
        if (kt + 1 < NS) {
            int kbase = (kt + 1) * BKT;
#pragma unroll
            for (int t = 0; t < 2; t++) {
                int v = tid + t * 256;
                int r = v >> 2;
                int kc = (v & 3) * 4;
                int grow = brow + r;
                pa[t] = (grow < M)
                    ? *(const float4*)(A + (size_t)grow * K_DIM + kbase + kc)
                    : make_float4(0.f, 0.f, 0.f, 0.f);
                int rb = v >> 5;
                int cb = (v & 31) * 4;
                pb[t] = *(const float4*)(Bw + (size_t)(kbase + rb) * BN + cb);
            }
        }

#pragma unroll
        for (int kh = 0; kh < 2; kh++) {
            const int k0 = kh * 8;
            uint32_t bfr[8][2];
#pragma unroll
            for (int nt = 0; nt < 8; nt++) {
                bfr[nt][0] = Bs[cur][k0 + tig][ncol0 + nt * 8 + gid];
                bfr[nt][1] = Bs[cur][k0 + tig + 4][ncol0 + nt * 8 + gid];
            }
#pragma unroll
            for (int mt = 0; mt < 2; mt++) {
                const int mb = mrow0 + mt * 16;
                uint32_t a0 = As[cur][k0 + tig][mb + gid];
                uint32_t a1 = As[cur][k0 + tig][mb + gid + 8];
                uint32_t a2 = As[cur][k0 + tig + 4][mb + gid];
                uint32_t a3 = As[cur][k0 + tig + 4][mb + gid + 8];
#pragma unroll
                for (int nt = 0; nt < 8; nt++) {
                    asm volatile(
                        "mma.sync.aligned.m16n8k8.row.col.f32.tf32.tf32.f32 "
                        "{%0,%1,%2,%3}, {%4,%5,%6,%7}, {%8,%9}, {%0,%1,%2,%3};"
                        : "+f"(acc[mt][nt][0]), "+f"(acc[mt][nt][1]),
                          "+f"(acc[mt][nt][2]), "+f"(acc[mt][nt][3])
                        : "r"(a0), "r"(a1), "r"(a2), "r"(a3),
                          "r"(bfr[nt][0]), "r"(bfr[nt][1]));
                }
            }
        }

        if (kt + 1 < NS) {
            __syncthreads();
#pragma unroll
            for (int t = 0; t < 2; t++) {
                int v = tid + t * 256;
                int r = v >> 2;
                int kc = (v & 3) * 4;
                As[nxt][kc + 0][r] = f2tf(pa[t].x);
                As[nxt][kc + 1][r] = f2tf(pa[t].y);
                As[nxt][kc + 2][r] = f2tf(pa[t].z);
                As[nxt][kc + 3][r] = f2tf(pa[t].w);
                int rb = v >> 5;
                int cb = (v & 31) * 4;
                Bs[nxt][rb][cb + 0] = f2tf(pb[t].x);
                Bs[nxt][rb][cb + 1] = f2tf(pb[t].y);
                Bs[nxt][rb][cb + 2] = f2tf(pb[t].z);
                Bs[nxt][rb][cb + 3] = f2tf(pb[t].w);
            }
            __syncthreads();
        }
    }

#pragma unroll
    for (int mt = 0; mt < 2; mt++) {
#pragma unroll
        for (int nt = 0; nt < 8; nt++) {
            int r0 = brow + mrow0 + mt * 16 + gid;
            int col = ncol0 + nt * 8 + 2 * tig;
            if (r0 < M) {
                __half2 p0 = __floats2half2_rn(acc[mt][nt][0], acc[mt][nt][1]);
                *(__half2*)(g_h + (size_t)r0 * H_DIM + col) = p0;
            }
            if (r0 + 8 < M) {
                __half2 p1 = __floats2half2_rn(acc[mt][nt][2], acc[mt][nt][3]);
                *(__half2*)(g_h + (size_t)(r0 + 8) * H_DIM + col) = p1;
            }
        }
    }
}

// ---------------- gather: 2 destinations per warp, LDG.128 per lane ----------
__device__ __forceinline__ void acc_half8(float acc[8], uint4 raw, float d) {
    __half2 h01 = *(__half2*)&raw.x;
    __half2 h23 = *(__half2*)&raw.y;
    __half2 h45 = *(__half2*)&raw.z;
    __half2 h67 = *(__half2*)&raw.w;
    float2 f01 = __half22float2(h01);
    float2 f23 = __half22float2(h23);
    float2 f45 = __half22float2(h45);
    float2 f67 = __half22float2(h67);
    acc[0] = fmaf(f01.x, d, acc[0]);
    acc[1] = fmaf(f01.y, d, acc[1]);
    acc[2] = fmaf(f23.x, d, acc[2]);
    acc[3] = fmaf(f23.y, d, acc[3]);
    acc[4] = fmaf(f45.x, d, acc[4]);
    acc[5] = fmaf(f45.y, d, acc[5]);
    acc[6] = fmaf(f67.x, d, acc[6]);
    acc[7] = fmaf(f67.y, d, acc[7]);
}

__global__ __launch_bounds__(256) void gather_kernel(const float* __restrict__ pb,
                                                     const float* __restrict__ pa,
                                                     float* __restrict__ out, int N) {
    const int gthread = blockIdx.x * blockDim.x + threadIdx.x;
    const int warp = gthread >> 5;
    const int lane = threadIdx.x & 31;
    const int half = lane >> 4;
    const int hl = lane & 15;
    const int c = warp * 2 + half;
    if (c >= N) return;

    const float dc = g_dinv[c];
    const int s = g_off[c];
    const int e = g_off[c + 1];

    float acc[8];
    {
        uint4 raw = *(const uint4*)(g_h + (size_t)c * H_DIM + hl * 8);
        __half2 h01 = *(__half2*)&raw.x;
        __half2 h23 = *(__half2*)&raw.y;
        __half2 h45 = *(__half2*)&raw.z;
        __half2 h67 = *(__half2*)&raw.w;
        float2 f01 = __half22float2(h01);
        float2 f23 = __half22float2(h23);
        float2 f45 = __half22float2(h45);
        float2 f67 = __half22float2(h67);
        acc[0] = f01.x * dc; acc[1] = f01.y * dc;
        acc[2] = f23.x * dc; acc[3] = f23.y * dc;
        acc[4] = f45.x * dc; acc[5] = f45.y * dc;
        acc[6] = f67.x * dc; acc[7] = f67.y * dc;
    }

    int i = s;
    for (; i + 3 < e; i += 4) {
        int s0 = g_src[i];
        int s1 = g_src[i + 1];
        int s2 = g_src[i + 2];
        int s3 = g_src[i + 3];
        float d0 = g_dinv[s0];
        float d1 = g_dinv[s1];
        float d2 = g_dinv[s2];
        float d3 = g_dinv[s3];
        uint4 v0 = *(const uint4*)(g_h + (size_t)s0 * H_DIM + hl * 8);
        uint4 v1 = *(const uint4*)(g_h + (size_t)s1 * H_DIM + hl * 8);
        uint4 v2 = *(const uint4*)(g_h + (size_t)s2 * H_DIM + hl * 8);
        uint4 v3 = *(const uint4*)(g_h + (size_t)s3 * H_DIM + hl * 8);
        acc_half8(acc, v0, d0);
        acc_half8(acc, v1, d1);
        acc_half8(acc, v2, d2);
        acc_half8(acc, v3, d3);
    }
    for (; i < e; i++) {
        int s0 = g_src[i];
        float d0 = g_dinv[s0];
        uint4 v0 = *(const uint4*)(g_h + (size_t)s0 * H_DIM + hl * 8);
        acc_half8(acc, v0, d0);
    }

    float4 bb0 = *(const float4*)(pb + hl * 8);
    float4 bb1 = *(const float4*)(pb + hl * 8 + 4);
    float4 aa0 = *(const float4*)(pa + hl * 8);
    float4 aa1 = *(const float4*)(pa + hl * 8 + 4);
    if (g_swap) {
        float4 t0 = bb0; bb0 = aa0; aa0 = t0;
        float4 t1 = bb1; bb1 = aa1; aa1 = t1;
    }
    float4 r0, r1;
    float t;
    t = fmaf(acc[0], dc, bb0.x); r0.x = (t >= 0.f) ? t : aa0.x * t;
    t = fmaf(acc[1], dc, bb0.y); r0.y = (t >= 0.f) ? t : aa0.y * t;
    t = fmaf(acc[2], dc, bb0.z); r0.z = (t >= 0.f) ? t : aa0.z * t;
    t = fmaf(acc[3], dc, bb0.w); r0.w = (t >= 0.f) ? t : aa0.w * t;
    t = fmaf(acc[4], dc, bb1.x); r1.x = (t >= 0.f) ? t : aa1.x * t;
    t = fmaf(acc[5], dc, bb1.y); r1.y = (t >= 0.f) ? t : aa1.y * t;
    t = fmaf(acc[6], dc, bb1.z); r1.z = (t >= 0.f) ? t : aa1.z * t;
    t = fmaf(acc[7], dc, bb1.w); r1.w = (t >= 0.f) ? t : aa1.w * t;
    *(float4*)(out + (size_t)c * H_DIM + hl * 8) = r0;
    *(float4*)(out + (size_t)c * H_DIM + hl * 8 + 4) = r1;
}

// ---------------- launch (fork-join: GEMM overlaps edge ingestion) ----------------
extern "C" void kernel_launch(void* const* d_in, const int* in_sizes, int n_in,
                              void* d_out, int out_size) {
    int ix = -1, ie = -1, iw = -1;
    for (int pass = 0; pass < 3; pass++) {
        int best = -1;
        long long bs = -1;
        for (int i = 0; i < n_in; i++) {
            if (i == ix || i == ie || i == iw) continue;
            if ((long long)in_sizes[i] > bs) { bs = in_sizes[i]; best = i; }
        }
        if (pass == 0) ix = best; else if (pass == 1) ie = best; else iw = best;
    }
    int ib = -1, ia = -1;
    for (int i = 0; i < n_in; i++) {
        if (i == ix || i == ie || i == iw) continue;
        if (ib < 0) ib = i; else ia = i;
    }

    const float* x = (const float*)d_in[ix];
    const int*   e = (const int*)d_in[ie];
    const float* W = (const float*)d_in[iw];
    const float* b = (const float*)d_in[ib];
    const float* alpha = (const float*)d_in[ia];
    float* out = (float*)d_out;

    const int N = in_sizes[ix] / K_DIM;   // 100000
    const int E = in_sizes[ie] / 2;       // 1600000
    const int NB = (N + SCAN_B - 1) / SCAN_B;
    const int TB = 256;

    static cudaStream_t s2 = nullptr;
    static cudaEvent_t evFork = nullptr, evJoin = nullptr;
    if (s2 == nullptr) {
        cudaStreamCreateWithFlags(&s2, cudaStreamNonBlocking);
        cudaEventCreateWithFlags(&evFork, cudaEventDisableTiming);
        cudaEventCreateWithFlags(&evJoin, cudaEventDisableTiming);
    }

    // fork: GEMM on s2 (depends on nothing device-side)
    cudaEventRecord(evFork, 0);
    cudaStreamWaitEvent(s2, evFork, 0);
    gemm_tf32_kernel<<<(N + BM - 1) / BM, 256, 0, s2>>>(x, W, N);
    cudaEventRecord(evJoin, s2);

    // edge ingestion chain on main stream (5 launches)
    init_kernel<<<(N + TB - 1) / TB, TB>>>(e, b, alpha, N);
    hist_kernel<<<(E + TB - 1) / TB, TB>>>(e, E, N);
    scanA_kernel<<<NB, SCAN_B>>>(N);
    scanC_kernel<<<(N + TB - 1) / TB, TB>>>(N);
    scatter_src_kernel<<<(E + TB - 1) / TB, TB>>>(e, E, N);

    // join, then gather (2 dests per warp => N*16 threads)
    cudaStreamWaitEvent(0, evJoin, 0);
    gather_kernel<<<(int)(((long long)N * 16 + TB - 1) / TB), TB>>>(b, alpha, out, N);
}

// round 17
// speedup vs baseline: 1.1262x; 1.0934x over previous
#include <cuda_runtime.h>
#include <cuda_fp16.h>
#include <cuda_bf16.h>
#include <cstdint>

#define N_NODES_MAX 100000
#define E_MAX       1600000
#define K_DIM       256
#define H_DIM       128
#define SCAN_B      1024
#define NB_MAX      ((N_NODES_MAX + SCAN_B - 1) / SCAN_B)   // 98

// ---------------- device scratch (static, no allocation) ----------------
__device__ __half g_h[(size_t)N_NODES_MAX * H_DIM];  // h = x@W (UNSCALED, fp16)
__device__ int    g_count[N_NODES_MAX];
__device__ int    g_off[N_NODES_MAX + 1];
__device__ float  g_dinv[N_NODES_MAX];
__device__ int    g_src[E_MAX];
__device__ int    g_rank[E_MAX];
__device__ int    g_bsum[NB_MAX + 1];
__device__ int    g_is64;
__device__ int    g_swap;

__device__ __forceinline__ int edge_val(const int* e, long long idx) {
    return g_is64 ? e[2 * idx] : e[(size_t)idx];
}

// ---------------- init: zero counts + dtype/order probe (fused) --------------
__global__ void init_kernel(const int* __restrict__ e,
                            const float* __restrict__ pb,
                            const float* __restrict__ pa, int n) {
    int i = blockIdx.x * blockDim.x + threadIdx.x;
    if (i < n) g_count[i] = 0;
    if (blockIdx.x == 0 && threadIdx.x < 32) {
        int lane = threadIdx.x;
        int nz = (e[2 * lane + 1] != 0) ? 1 : 0;
        unsigned m = __ballot_sync(0xFFFFFFFFu, nz);
        if (lane == 0) {
            g_is64 = (m == 0u) ? 1 : 0;
            g_swap = (pb[0] != 0.0f && pa[0] == 0.0f) ? 1 : 0;
        }
    }
}

// ---------------- hist + per-edge rank (atomic return value) -----------------
__global__ void hist_kernel(const int* __restrict__ e, int E, int N) {
    int i = blockIdx.x * blockDim.x + threadIdx.x;
    if (i >= E) return;
    unsigned c = (unsigned)edge_val(e, (long long)E + i);
    int rk = 0;
    if (c < (unsigned)N) rk = atomicAdd(&g_count[c], 1);
    g_rank[i] = rk;
}

__global__ __launch_bounds__(SCAN_B) void scanA_kernel(int N) {
    __shared__ int sm[SCAN_B];
    const int tid = threadIdx.x;
    const int i = blockIdx.x * SCAN_B + tid;
    int v = (i < N) ? g_count[i] : 0;
    sm[tid] = v;
    __syncthreads();
#pragma unroll
    for (int d = 1; d < SCAN_B; d <<= 1) {
        int t = sm[tid];
        int add = (tid >= d) ? sm[tid - d] : 0;
        __syncthreads();
        sm[tid] = t + add;
        __syncthreads();
    }
    if (i < N) g_off[i] = sm[tid] - v;
    if (tid == SCAN_B - 1) g_bsum[blockIdx.x] = sm[tid];
}

// scanC: inline bsum-prefix + finalize off + dinv.
__global__ void scanC_kernel(int N) {
    __shared__ int base_sh;
    const int bucket = blockIdx.x >> 2;
    if (threadIdx.x < 32) {
        int s = 0;
        for (int j = threadIdx.x; j < bucket; j += 32) s += g_bsum[j];
#pragma unroll
        for (int o = 16; o; o >>= 1) s += __shfl_down_sync(0xFFFFFFFFu, s, o);
        if (threadIdx.x == 0) base_sh = s;
    }
    __syncthreads();
    int i = blockIdx.x * blockDim.x + threadIdx.x;
    if (i >= N) return;
    int cnt = g_count[i];
    int off = g_off[i] + base_sh;
    g_off[i] = off;
    g_dinv[i] = rsqrtf((float)cnt + 1.0f);
    if (i == N - 1) g_off[N] = off + cnt;
}

// ---------------- scatter: NO atomics (uses precomputed rank) ----------------
__global__ void scatter_src_kernel(const int* __restrict__ e, int E, int N) {
    int i = blockIdx.x * blockDim.x + threadIdx.x;
    if (i >= E) return;
    unsigned r = (unsigned)edge_val(e, i);
    unsigned c = (unsigned)edge_val(e, (long long)E + i);
    if (r < (unsigned)N && c < (unsigned)N) {
        int p = g_off[c] + g_rank[i];
        if ((unsigned)p < (unsigned)E_MAX) g_src[p] = (int)r;
    }
}

// ---------------- fp16 tensor-core GEMM: g_h = x @ W (fp16 out) --------------
// CTA 128x128, 8 warps (4M x 2N), warp tile 32x64, k-slice 16, double buffer.
// mma.m16n8k16.f16 with fp32 accumulate; smem holds half2 k-pairs.
#define BM 128
#define BN 128
#define BKT 16
#define SMP (BM + 8)   // half2 stride: fragment bank = 8*tig + gid, conflict-free

__device__ __forceinline__ uint32_t f2h2(float lo, float hi) {
    __half2 h = __floats2half2_rn(lo, hi);
    return *(uint32_t*)&h;
}

__global__ __launch_bounds__(256) void gemm_f16_kernel(const float* __restrict__ A,
                                                       const float* __restrict__ Bw,
                                                       int M) {
    __shared__ uint32_t As[2][BKT / 2][SMP];   // [buf][kpair][m] (half2)
    __shared__ uint32_t Bs[2][BKT / 2][SMP];   // [buf][kpair][n] (half2)
    const int tid = threadIdx.x;
    const int brow = blockIdx.x * BM;
    const int wid = tid >> 5;
    const int lane = tid & 31;
    const int gid = lane >> 2;       // 0..7
    const int tig = lane & 3;        // 0..3
    const int mrow0 = (wid & 3) * 32;
    const int ncol0 = (wid >> 2) * 64;

    // B staging task (single pass: 256 tasks)
    const int bkp = tid >> 5;        // 0..7 (k-pair)
    const int bc4 = (tid & 31) * 4;  // 0..124 (n)

    float acc[2][8][4];
#pragma unroll
    for (int mt = 0; mt < 2; mt++)
#pragma unroll
        for (int nt = 0; nt < 8; nt++)
#pragma unroll
            for (int q = 0; q < 4; q++) acc[mt][nt][q] = 0.0f;

    // ---- stage slice 0 into buffer 0 ----
#pragma unroll
    for (int t = 0; t < 2; t++) {
        int v = tid + t * 256;
        int r = v >> 2;
        int kc = (v & 3) * 4;
        int grow = brow + r;
        float4 a = (grow < M) ? *(const float4*)(A + (size_t)grow * K_DIM + kc)
                              : make_float4(0.f, 0.f, 0.f, 0.f);
        As[0][(kc >> 1) + 0][r] = f2h2(a.x, a.y);
        As[0][(kc >> 1) + 1][r] = f2h2(a.z, a.w);
    }
    {
        float4 b0 = *(const float4*)(Bw + (size_t)(2 * bkp) * BN + bc4);
        float4 b1 = *(const float4*)(Bw + (size_t)(2 * bkp + 1) * BN + bc4);
        uint4 pk;
        pk.x = f2h2(b0.x, b1.x);
        pk.y = f2h2(b0.y, b1.y);
        pk.z = f2h2(b0.z, b1.z);
        pk.w = f2h2(b0.w, b1.w);
        *(uint4*)&Bs[0][bkp][bc4] = pk;
    }
    __syncthreads();

    const int NS = K_DIM / BKT;      // 16
    for (int kt = 0; kt < NS; kt++) {
        const int cur = kt & 1;
        const int nxt = cur ^ 1;

        // prefetch next slice into registers
        float4 pa[2], pb0, pb1;
        if (kt + 1 < NS) {
            int kbase = (kt + 1) * BKT;
#pragma unroll
            for (int t = 0; t < 2; t++) {
                int v = tid + t * 256;
                int r = v >> 2;
                int kc = (v & 3) * 4;
                int grow = brow + r;
                pa[t] = (grow < M)
                    ? *(const float4*)(A + (size_t)grow * K_DIM + kbase + kc)
                    : make_float4(0.f, 0.f, 0.f, 0.f);
            }
            pb0 = *(const float4*)(Bw + (size_t)(kbase + 2 * bkp) * BN + bc4);
            pb1 = *(const float4*)(Bw + (size_t)(kbase + 2 * bkp + 1) * BN + bc4);
        }

        // compute: one m16n8k16 per (mt, nt) covers the whole 16-wide slice
        uint32_t bfr[8][2];
#pragma unroll
        for (int nt = 0; nt < 8; nt++) {
            bfr[nt][0] = Bs[cur][tig][ncol0 + nt * 8 + gid];
            bfr[nt][1] = Bs[cur][tig + 4][ncol0 + nt * 8 + gid];
        }
#pragma unroll
        for (int mt = 0; mt < 2; mt++) {
            const int mb = mrow0 + mt * 16;
            uint32_t a0 = As[cur][tig][mb + gid];
            uint32_t a1 = As[cur][tig][mb + gid + 8];
            uint32_t a2 = As[cur][tig + 4][mb + gid];
            uint32_t a3 = As[cur][tig + 4][mb + gid + 8];
#pragma unroll
            for (int nt = 0; nt < 8; nt++) {
                asm volatile(
                    "mma.sync.aligned.m16n8k16.row.col.f32.f16.f16.f32 "
                    "{%0,%1,%2,%3}, {%4,%5,%6,%7}, {%8,%9}, {%0,%1,%2,%3};"
                    : "+f"(acc[mt][nt][0]), "+f"(acc[mt][nt][1]),
                      "+f"(acc[mt][nt][2]), "+f"(acc[mt][nt][3])
                    : "r"(a0), "r"(a1), "r"(a2), "r"(a3),
                      "r"(bfr[nt][0]), "r"(bfr[nt][1]));
            }
        }

        if (kt + 1 < NS) {
            __syncthreads();   // all warps done with old buffer contents
#pragma unroll
            for (int t = 0; t < 2; t++) {
                int v = tid + t * 256;
                int r = v >> 2;
                int kc = (v & 3) * 4;
                As[nxt][(kc >> 1) + 0][r] = f2h2(pa[t].x, pa[t].y);
                As[nxt][(kc >> 1) + 1][r] = f2h2(pa[t].z, pa[t].w);
            }
            {
                uint4 pk;
                pk.x = f2h2(pb0.x, pb1.x);
                pk.y = f2h2(pb0.y, pb1.y);
                pk.z = f2h2(pb0.z, pb1.z);
                pk.w = f2h2(pb0.w, pb1.w);
                *(uint4*)&Bs[nxt][bkp][bc4] = pk;
            }
            __syncthreads();   // stores visible before next iteration reads
        }
    }

    // ---- epilogue: convert to fp16, store (same D layout as tf32 version) ----
#pragma unroll
    for (int mt = 0; mt < 2; mt++) {
#pragma unroll
        for (int nt = 0; nt < 8; nt++) {
            int r0 = brow + mrow0 + mt * 16 + gid;
            int col = ncol0 + nt * 8 + 2 * tig;
            if (r0 < M) {
                __half2 p0 = __floats2half2_rn(acc[mt][nt][0], acc[mt][nt][1]);
                *(__half2*)(g_h + (size_t)r0 * H_DIM + col) = p0;
            }
            if (r0 + 8 < M) {
                __half2 p1 = __floats2half2_rn(acc[mt][nt][2], acc[mt][nt][3]);
                *(__half2*)(g_h + (size_t)(r0 + 8) * H_DIM + col) = p1;
            }
        }
    }
}

// ---------------- gather: 2 destinations per warp, LDG.128 per lane ----------
__device__ __forceinline__ void acc_half8(float acc[8], uint4 raw, float d) {
    __half2 h01 = *(__half2*)&raw.x;
    __half2 h23 = *(__half2*)&raw.y;
    __half2 h45 = *(__half2*)&raw.z;
    __half2 h67 = *(__half2*)&raw.w;
    float2 f01 = __half22float2(h01);
    float2 f23 = __half22float2(h23);
    float2 f45 = __half22float2(h45);
    float2 f67 = __half22float2(h67);
    acc[0] = fmaf(f01.x, d, acc[0]);
    acc[1] = fmaf(f01.y, d, acc[1]);
    acc[2] = fmaf(f23.x, d, acc[2]);
    acc[3] = fmaf(f23.y, d, acc[3]);
    acc[4] = fmaf(f45.x, d, acc[4]);
    acc[5] = fmaf(f45.y, d, acc[5]);
    acc[6] = fmaf(f67.x, d, acc[6]);
    acc[7] = fmaf(f67.y, d, acc[7]);
}

__global__ __launch_bounds__(256) void gather_kernel(const float* __restrict__ pb,
                                                     const float* __restrict__ pa,
                                                     float* __restrict__ out, int N) {
    const int gthread = blockIdx.x * blockDim.x + threadIdx.x;
    const int warp = gthread >> 5;
    const int lane = threadIdx.x & 31;
    const int half = lane >> 4;
    const int hl = lane & 15;
    const int c = warp * 2 + half;
    if (c >= N) return;

    const float dc = g_dinv[c];
    const int s = g_off[c];
    const int e = g_off[c + 1];

    float acc[8];
    {
        uint4 raw = *(const uint4*)(g_h + (size_t)c * H_DIM + hl * 8);
        __half2 h01 = *(__half2*)&raw.x;
        __half2 h23 = *(__half2*)&raw.y;
        __half2 h45 = *(__half2*)&raw.z;
        __half2 h67 = *(__half2*)&raw.w;
        float2 f01 = __half22float2(h01);
        float2 f23 = __half22float2(h23);
        float2 f45 = __half22float2(h45);
        float2 f67 = __half22float2(h67);
        acc[0] = f01.x * dc; acc[1] = f01.y * dc;
        acc[2] = f23.x * dc; acc[3] = f23.y * dc;
        acc[4] = f45.x * dc; acc[5] = f45.y * dc;
        acc[6] = f67.x * dc; acc[7] = f67.y * dc;
    }

    int i = s;
    for (; i + 3 < e; i += 4) {
        int s0 = g_src[i];
        int s1 = g_src[i + 1];
        int s2 = g_src[i + 2];
        int s3 = g_src[i + 3];
        float d0 = g_dinv[s0];
        float d1 = g_dinv[s1];
        float d2 = g_dinv[s2];
        float d3 = g_dinv[s3];
        uint4 v0 = *(const uint4*)(g_h + (size_t)s0 * H_DIM + hl * 8);
        uint4 v1 = *(const uint4*)(g_h + (size_t)s1 * H_DIM + hl * 8);
        uint4 v2 = *(const uint4*)(g_h + (size_t)s2 * H_DIM + hl * 8);
        uint4 v3 = *(const uint4*)(g_h + (size_t)s3 * H_DIM + hl * 8);
        acc_half8(acc, v0, d0);
        acc_half8(acc, v1, d1);
        acc_half8(acc, v2, d2);
        acc_half8(acc, v3, d3);
    }
    for (; i < e; i++) {
        int s0 = g_src[i];
        float d0 = g_dinv[s0];
        uint4 v0 = *(const uint4*)(g_h + (size_t)s0 * H_DIM + hl * 8);
        acc_half8(acc, v0, d0);
    }

    float4 bb0 = *(const float4*)(pb + hl * 8);
    float4 bb1 = *(const float4*)(pb + hl * 8 + 4);
    float4 aa0 = *(const float4*)(pa + hl * 8);
    float4 aa1 = *(const float4*)(pa + hl * 8 + 4);
    if (g_swap) {
        float4 t0 = bb0; bb0 = aa0; aa0 = t0;
        float4 t1 = bb1; bb1 = aa1; aa1 = t1;
    }
    float4 r0, r1;
    float t;
    t = fmaf(acc[0], dc, bb0.x); r0.x = (t >= 0.f) ? t : aa0.x * t;
    t = fmaf(acc[1], dc, bb0.y); r0.y = (t >= 0.f) ? t : aa0.y * t;
    t = fmaf(acc[2], dc, bb0.z); r0.z = (t >= 0.f) ? t : aa0.z * t;
    t = fmaf(acc[3], dc, bb0.w); r0.w = (t >= 0.f) ? t : aa0.w * t;
    t = fmaf(acc[4], dc, bb1.x); r1.x = (t >= 0.f) ? t : aa1.x * t;
    t = fmaf(acc[5], dc, bb1.y); r1.y = (t >= 0.f) ? t : aa1.y * t;
    t = fmaf(acc[6], dc, bb1.z); r1.z = (t >= 0.f) ? t : aa1.z * t;
    t = fmaf(acc[7], dc, bb1.w); r1.w = (t >= 0.f) ? t : aa1.w * t;
    *(float4*)(out + (size_t)c * H_DIM + hl * 8) = r0;
    *(float4*)(out + (size_t)c * H_DIM + hl * 8 + 4) = r1;
}

// ---------------- launch (fork-join: GEMM overlaps edge ingestion) ----------------
extern "C" void kernel_launch(void* const* d_in, const int* in_sizes, int n_in,
                              void* d_out, int out_size) {
    int ix = -1, ie = -1, iw = -1;
    for (int pass = 0; pass < 3; pass++) {
        int best = -1;
        long long bs = -1;
        for (int i = 0; i < n_in; i++) {
            if (i == ix || i == ie || i == iw) continue;
            if ((long long)in_sizes[i] > bs) { bs = in_sizes[i]; best = i; }
        }
        if (pass == 0) ix = best; else if (pass == 1) ie = best; else iw = best;
    }
    int ib = -1, ia = -1;
    for (int i = 0; i < n_in; i++) {
        if (i == ix || i == ie || i == iw) continue;
        if (ib < 0) ib = i; else ia = i;
    }

    const float* x = (const float*)d_in[ix];
    const int*   e = (const int*)d_in[ie];
    const float* W = (const float*)d_in[iw];
    const float* b = (const float*)d_in[ib];
    const float* alpha = (const float*)d_in[ia];
    float* out = (float*)d_out;

    const int N = in_sizes[ix] / K_DIM;   // 100000
    const int E = in_sizes[ie] / 2;       // 1600000
    const int NB = (N + SCAN_B - 1) / SCAN_B;
    const int TB = 256;

    static cudaStream_t s2 = nullptr;
    static cudaEvent_t evFork = nullptr, evJoin = nullptr;
    if (s2 == nullptr) {
        cudaStreamCreateWithFlags(&s2, cudaStreamNonBlocking);
        cudaEventCreateWithFlags(&evFork, cudaEventDisableTiming);
        cudaEventCreateWithFlags(&evJoin, cudaEventDisableTiming);
    }

    // fork: GEMM on s2 (depends on nothing device-side)
    cudaEventRecord(evFork, 0);
    cudaStreamWaitEvent(s2, evFork, 0);
    gemm_f16_kernel<<<(N + BM - 1) / BM, 256, 0, s2>>>(x, W, N);
    cudaEventRecord(evJoin, s2);

    // edge ingestion chain on main stream (5 launches)
    init_kernel<<<(N + TB - 1) / TB, TB>>>(e, b, alpha, N);
    hist_kernel<<<(E + TB - 1) / TB, TB>>>(e, E, N);
    scanA_kernel<<<NB, SCAN_B>>>(N);
    scanC_kernel<<<(N + TB - 1) / TB, TB>>>(N);
    scatter_src_kernel<<<(E + TB - 1) / TB, TB>>>(e, E, N);

    // join, then gather (2 dests per warp => N*16 threads)
    cudaStreamWaitEvent(0, evJoin, 0);
    gather_kernel<<<(int)(((long long)N * 16 + TB - 1) / TB), TB>>>(b, alpha, out, N);
}